// round 15
// baseline (speedup 1.0000x reference)
#include <cuda_runtime.h>
#include <cstdint>
#include <math.h>

// Shapes (fixed by the problem)
#define LL   1024
#define BSZ  4
#define DD   1024
#define NHH  16
#define DHH  64
#define PD   2048          // 2*D
#define RR   4096          // L*BS
#define NB   64            // BS*NH batch count for attention

// Scratch (device globals: allocation-free kernel_launch)
__device__ float g_proj[(size_t)RR * PD];            // 32 MB (tf32-rounded)
__device__ float g_hid [(size_t)NHH * RR * LL];      // 268 MB (tf32-rounded)
__device__ float g_outcat[(size_t)RR * DD];          // 17 MB (tf32-rounded)
__device__ float g_w1t[(size_t)NHH * LL * DHH];      // 4 MB  (rounded)
__device__ float g_w2t[(size_t)NHH * LL * LL];       // 64 MB (rounded)
__device__ float g_xr [(size_t)RR * DD];             // 16 MB (x rounded)
__device__ float g_wir[(size_t)PD * DD];             // 8 MB  (Wi rounded)
__device__ float g_wor[(size_t)DD * DD];             // 4 MB  (Wo rounded)
__device__ float g_vt [(size_t)BSZ * LL * LL];       // 16 MB (V^T per batch, rounded)

// ---------------------------------------------------------------------------
__device__ __forceinline__ uint32_t f2tf32(float f) {
    uint32_t u;
    asm("cvt.rna.tf32.f32 %0, %1;" : "=r"(u) : "f"(f));
    return u;
}
__device__ __forceinline__ float rndf(float f) { return __uint_as_float(f2tf32(f)); }

__device__ __forceinline__ uint32_t smem_u32(const void* p) {
    uint32_t a;
    asm("{ .reg .u64 t; cvta.to.shared.u64 t, %1; cvt.u32.u64 %0, t; }" : "=r"(a) : "l"(p));
    return a;
}
__device__ __forceinline__ void cp_async16(uint32_t dst, const void* src) {
    asm volatile("cp.async.cg.shared.global [%0], [%1], 16;" :: "r"(dst), "l"(src));
}
__device__ __forceinline__ void cp_commit() {
    asm volatile("cp.async.commit_group;" ::: "memory");
}
__device__ __forceinline__ void cp_wait1() {
    asm volatile("cp.async.wait_group 1;" ::: "memory");
}
__device__ __forceinline__ void ldsm4(uint32_t& r0, uint32_t& r1, uint32_t& r2, uint32_t& r3,
                                      uint32_t addr) {
    asm volatile("ldmatrix.sync.aligned.m8n8.x4.shared.b16 {%0,%1,%2,%3}, [%4];"
                 : "=r"(r0), "=r"(r1), "=r"(r2), "=r"(r3) : "r"(addr));
}
__device__ __forceinline__ void mma_tf32(float c[4], const uint32_t a[4], const uint32_t b[2]) {
    asm volatile(
        "mma.sync.aligned.m16n8k8.row.col.f32.tf32.tf32.f32 "
        "{%0,%1,%2,%3}, {%4,%5,%6,%7}, {%8,%9}, {%0,%1,%2,%3};"
        : "+f"(c[0]), "+f"(c[1]), "+f"(c[2]), "+f"(c[3])
        : "r"(a[0]), "r"(a[1]), "r"(a[2]), "r"(a[3]), "r"(b[0]), "r"(b[1]));
}

#define PADK 36
#define TS   (16 * PADK * 4)                 // 16-row block stride (std smem)
#define PS_LD 132                            // padded row length for P/V tiles
#define TSP  (16 * PS_LD * 4)                // 16-row block stride (P/V smem)

// ---------------------------------------------------------------------------
// Generic 128x128-tile tf32 GEMM: C = act(A @ B^T + bias). Pre-rounded inputs.
// 3-stage cp.async, ldmatrix, frag double-buffer. 8 warps (4M x 2N).
// mode: 0=proj  1=hid(relu)  3=out
// ---------------------------------------------------------------------------
#define STAGE_F (128 * PADK)
#define SMEM_BYTES (2 * 3 * STAGE_F * 4)     // 110592

__global__ void __launch_bounds__(256, 2) gemm_mma(
    int mode, int K, int relu,
    const float* __restrict__ Ain, const float* __restrict__ Bin,
    const float* __restrict__ biasIn, float* __restrict__ Cout)
{
    const int bm = blockIdx.y * 128;
    const int bn = blockIdx.x * 128;

    const float* A; const float* B; const float* bias; float* C;
    size_t sA, sB, ldc;
    if (mode == 0) {            // proj = x @ Wi^T + bi
        A = Ain; sA = DD; B = Bin; sB = DD; bias = biasIn; C = Cout; ldc = PD;
    } else if (mode == 1) {     // hid[h] = relu(proj[:, h*64:] @ w1t[h]^T + b1[h])
        int h = blockIdx.z;
        A = Ain + h * DHH;                sA = PD;
        B = Bin + (size_t)h * LL * DHH;   sB = DHH;
        bias = biasIn + h * LL;
        C = Cout + (size_t)h * RR * LL;   ldc = LL;
    } else {                    // out = outcat @ Wo^T + bo
        A = Ain; sA = DD; B = Bin; sB = DD; bias = biasIn; C = Cout; ldc = DD;
    }

    extern __shared__ __align__(16) float smem[];
    float* As = smem;                    // [3][128][PADK]
    float* Bs = smem + 3 * STAGE_F;      // [3][128][PADK]

    const int tid   = threadIdx.x;
    const int wid   = tid >> 5, lane = tid & 31;
    const int warpM = wid & 3;
    const int warpN = wid >> 2;
    const int grp   = lane >> 2;
    const int quad  = lane & 3;

    const int T = K / 32;

    const uint32_t sA0 = smem_u32(As);
    const uint32_t sB0 = smem_u32(Bs);
    const uint32_t aRow = (uint32_t)(((warpM * 32 + (lane & 15)) * PADK + (lane >> 4) * 4) * 4);
    const uint32_t bRow = (uint32_t)(((warpN * 64 + ((lane >> 4) & 1) * 8 + (lane & 7)) * PADK
                                      + ((lane >> 3) & 1) * 4) * 4);

    auto issue = [&](int chunk, int buf) {
        const int k0 = chunk * 32;
        float* sa = As + buf * STAGE_F;
        float* sb = Bs + buf * STAGE_F;
#pragma unroll
        for (int j = 0; j < 4; j++) {
            const int idx = tid + j * 256;
            const int r = idx >> 3, c4 = (idx & 7) * 4;
            cp_async16(smem_u32(&sa[r * PADK + c4]),
                       &A[(size_t)(bm + r) * sA + k0 + c4]);
            cp_async16(smem_u32(&sb[r * PADK + c4]),
                       &B[(size_t)(bn + r) * sB + k0 + c4]);
        }
    };

    issue(0, 0); cp_commit();
    if (1 < T) issue(1, 1);
    cp_commit();

    float acc[2][8][4] = {};
    uint32_t af[2][2][4], bf[2][8][2];

#pragma unroll 1
    for (int t = 0; t < T; t++) {
        cp_wait1();
        __syncthreads();

        if (t + 2 < T) issue(t + 2, (t + 2) % 3);
        cp_commit();

        const uint32_t aSt = sA0 + (uint32_t)((t % 3) * STAGE_F * 4);
        const uint32_t bSt = sB0 + (uint32_t)((t % 3) * STAGE_F * 4);

#pragma unroll
        for (int mt = 0; mt < 2; mt++)
            ldsm4(af[0][mt][0], af[0][mt][1], af[0][mt][2], af[0][mt][3],
                  aSt + aRow + mt * TS);
#pragma unroll
        for (int p = 0; p < 4; p++)
            ldsm4(bf[0][2*p][0], bf[0][2*p][1], bf[0][2*p+1][0], bf[0][2*p+1][1],
                  bSt + bRow + p * TS);

#pragma unroll
        for (int ks = 0; ks < 4; ks++) {
            const int cur = ks & 1, nxt = cur ^ 1;
            if (ks < 3) {
                const uint32_t ko = (uint32_t)((ks + 1) * 32);
#pragma unroll
                for (int mt = 0; mt < 2; mt++)
                    ldsm4(af[nxt][mt][0], af[nxt][mt][1], af[nxt][mt][2], af[nxt][mt][3],
                          aSt + aRow + mt * TS + ko);
#pragma unroll
                for (int p = 0; p < 4; p++)
                    ldsm4(bf[nxt][2*p][0], bf[nxt][2*p][1], bf[nxt][2*p+1][0], bf[nxt][2*p+1][1],
                          bSt + bRow + p * TS + ko);
            }
#pragma unroll
            for (int mt = 0; mt < 2; mt++)
#pragma unroll
                for (int nt = 0; nt < 8; nt++)
                    mma_tf32(acc[mt][nt], af[cur][mt], bf[cur][nt]);
        }
    }

    const bool rnd_out = (mode < 2);
#pragma unroll
    for (int mt = 0; mt < 2; mt++) {
        const int m = bm + warpM * 32 + mt * 16 + grp;
#pragma unroll
        for (int nt = 0; nt < 8; nt++) {
            const int n = bn + warpN * 64 + nt * 8 + quad * 2;
            float b0 = bias[n], b1 = bias[n + 1];
            float2 v0 = make_float2(acc[mt][nt][0] + b0, acc[mt][nt][1] + b1);
            float2 v1 = make_float2(acc[mt][nt][2] + b0, acc[mt][nt][3] + b1);
            if (relu) {
                v0.x = fmaxf(v0.x, 0.f); v0.y = fmaxf(v0.y, 0.f);
                v1.x = fmaxf(v1.x, 0.f); v1.y = fmaxf(v1.y, 0.f);
            }
            if (rnd_out) {
                v0.x = rndf(v0.x); v0.y = rndf(v0.y);
                v1.x = rndf(v1.x); v1.y = rndf(v1.y);
            }
            *(float2*)&C[(size_t)m * ldc + n]       = v0;
            *(float2*)&C[(size_t)(m + 8) * ldc + n] = v1;
        }
    }
}

// ---------------------------------------------------------------------------
// Fused logits + online-softmax + PV, 512 threads (16 warps = full SM).
// S tile 128x128: warps 4M x 4N (32x32). O tile 128x64: warps 4M x 4N (32x16).
// Diagonal warp-tile skip: on tj==ti, warp tiles with warpN > warpM are fully
// above the causal boundary -> skip their S-phase ldsm+mma entirely (their
// outputs are already forced to 0 by the ok0/ok1 masks; bit-identical result).
// ---------------------------------------------------------------------------
#define ATTN_SMEM_BYTES ((2 * 3 * STAGE_F + 128 * PS_LD + 64 * PS_LD + 3 * 128 + 2 * 512) * 4)

__global__ void __launch_bounds__(512, 1) attn_fused(const float* __restrict__ b2)
{
    const int bx = blockIdx.x;
    const int ti = 7 - (bx >> 6);              // ti-major: heaviest wave first
    const int i  = bx & 63;
    const int kq = i >> 2, bq = i & 3;
    const int bv = i >> 4, kv = i & 15;
    const int bm = ti * 128;

    const float* Ahid = g_hid + (size_t)kq * RR * LL + bq * LL;    // stride 4*LL
    const float* Bw   = g_w2t + (size_t)kq * LL * LL;              // stride LL
    const float* bias = b2 + kq * LL;
    const float* Vt   = g_vt + (size_t)bv * LL * LL + (size_t)(kv * DHH) * LL;

    extern __shared__ __align__(16) float smem[];
    float* As    = smem;                       // [3][128][PADK]
    float* Bs    = As + 3 * STAGE_F;           // [3][128][PADK]
    float* Ps    = Bs + 3 * STAGE_F;           // [128][PS_LD]
    float* Vs    = Ps + 128 * PS_LD;           // [64][PS_LD]
    float* run_m = Vs + 64 * PS_LD;            // [128]
    float* run_s = run_m + 128;                // [128]
    float* resc  = run_s + 128;                // [128]
    float* pmax  = resc + 128;                 // [4][128]
    float* psum  = pmax + 512;                 // [4][128]

    const int tid   = threadIdx.x;
    const int wid   = tid >> 5, lane = tid & 31;
    const int warpM = wid & 3, warpN = wid >> 2;      // 4 x 4 warps
    const int grp   = lane >> 2, quad = lane & 3;

    if (tid < 128) { run_m[tid] = -1e30f; run_s[tid] = 0.f; }

    const uint32_t sA0 = smem_u32(As);
    const uint32_t sB0 = smem_u32(Bs);
    const uint32_t sP0 = smem_u32(Ps);
    const uint32_t sV0 = smem_u32(Vs);
    const uint32_t aRow = (uint32_t)(((warpM * 32 + (lane & 15)) * PADK + (lane >> 4) * 4) * 4);
    const uint32_t bRow = (uint32_t)(((warpN * 32 + ((lane >> 4) & 1) * 8 + (lane & 7)) * PADK
                                      + ((lane >> 3) & 1) * 4) * 4);
    const uint32_t paRow = (uint32_t)(((warpM * 32 + (lane & 15)) * PS_LD + (lane >> 4) * 4) * 4);
    const uint32_t pbRow = (uint32_t)(((warpN * 16 + ((lane >> 4) & 1) * 8 + (lane & 7)) * PS_LD
                                       + ((lane >> 3) & 1) * 4) * 4);

    float acc_o[2][2][4] = {};
    __syncthreads();

    for (int tj = 0; tj <= ti; tj++) {
        const int bn = tj * 128;
        const bool diag = (tj == ti);
        // warp tiles entirely above the causal boundary do no S-phase math
        const bool active = !diag || (warpN <= warpM);

        // V tile: 64 rows x 128 cols = 2048 float4 (4 per thread).
#pragma unroll
        for (int j = 0; j < 4; j++) {
            const int idx = tid + j * 512;
            const int d = idx >> 5, c4 = (idx & 31) * 4;
            cp_async16(smem_u32(&Vs[d * PS_LD + c4]), &Vt[(size_t)d * LL + bn + c4]);
        }
        cp_commit();

        auto issueS = [&](int chunk, int buf) {
            const int k0 = chunk * 32;
            float* sa = As + buf * STAGE_F;
            float* sb = Bs + buf * STAGE_F;
#pragma unroll
            for (int j = 0; j < 2; j++) {
                const int idx = tid + j * 512;
                const int r = idx >> 3, c4 = (idx & 7) * 4;
                cp_async16(smem_u32(&sa[r * PADK + c4]),
                           &Ahid[(size_t)(bm + r) * (4 * LL) + k0 + c4]);
                cp_async16(smem_u32(&sb[r * PADK + c4]),
                           &Bw[(size_t)(bn + r) * LL + k0 + c4]);
            }
        };
        issueS(0, 0); cp_commit();
        issueS(1, 1); cp_commit();

        float acc[2][4][4] = {};
        {
            uint32_t af[2][2][4], bf[2][4][2];
#pragma unroll 1
            for (int t = 0; t < 32; t++) {
                cp_wait1();
                __syncthreads();
                if (t + 2 < 32) issueS(t + 2, (t + 2) % 3);
                cp_commit();

                if (active) {
                    const uint32_t aSt = sA0 + (uint32_t)((t % 3) * STAGE_F * 4);
                    const uint32_t bSt = sB0 + (uint32_t)((t % 3) * STAGE_F * 4);

#pragma unroll
                    for (int mt = 0; mt < 2; mt++)
                        ldsm4(af[0][mt][0], af[0][mt][1], af[0][mt][2], af[0][mt][3],
                              aSt + aRow + mt * TS);
#pragma unroll
                    for (int p = 0; p < 2; p++)
                        ldsm4(bf[0][2*p][0], bf[0][2*p][1], bf[0][2*p+1][0], bf[0][2*p+1][1],
                              bSt + bRow + p * TS);

#pragma unroll
                    for (int ks = 0; ks < 4; ks++) {
                        const int cur = ks & 1, nxt = cur ^ 1;
                        if (ks < 3) {
                            const uint32_t ko = (uint32_t)((ks + 1) * 32);
#pragma unroll
                            for (int mt = 0; mt < 2; mt++)
                                ldsm4(af[nxt][mt][0], af[nxt][mt][1], af[nxt][mt][2], af[nxt][mt][3],
                                      aSt + aRow + mt * TS + ko);
#pragma unroll
                            for (int p = 0; p < 2; p++)
                                ldsm4(bf[nxt][2*p][0], bf[nxt][2*p][1],
                                      bf[nxt][2*p+1][0], bf[nxt][2*p+1][1],
                                      bSt + bRow + p * TS + ko);
                        }
#pragma unroll
                        for (int mt = 0; mt < 2; mt++)
#pragma unroll
                            for (int nt = 0; nt < 4; nt++)
                                mma_tf32(acc[mt][nt], af[cur][mt], bf[cur][nt]);
                    }
                }
            }
        }

        // ---- bias + online-softmax stats ----
#pragma unroll
        for (int nt = 0; nt < 4; nt++) {
            const int n = bn + warpN * 32 + nt * 8 + quad * 2;
            const float bb0 = bias[n], bb1 = bias[n + 1];
            acc[0][nt][0] += bb0; acc[0][nt][1] += bb1;
            acc[0][nt][2] += bb0; acc[0][nt][3] += bb1;
            acc[1][nt][0] += bb0; acc[1][nt][1] += bb1;
            acc[1][nt][2] += bb0; acc[1][nt][3] += bb1;
        }

        float mx[2][2];
#pragma unroll
        for (int mt = 0; mt < 2; mt++)
#pragma unroll
            for (int p = 0; p < 2; p++) {
                const int row = warpM * 32 + mt * 16 + grp + p * 8;
                float m = -1e30f;
#pragma unroll
                for (int nt = 0; nt < 4; nt++) {
                    const int n = warpN * 32 + nt * 8 + quad * 2;
                    if (!diag || n     <= row) m = fmaxf(m, acc[mt][nt][p * 2 + 0]);
                    if (!diag || n + 1 <= row) m = fmaxf(m, acc[mt][nt][p * 2 + 1]);
                }
                mx[mt][p] = m;
            }
#pragma unroll
        for (int o = 1; o <= 2; o <<= 1)
#pragma unroll
            for (int mt = 0; mt < 2; mt++) {
                mx[mt][0] = fmaxf(mx[mt][0], __shfl_xor_sync(0xFFFFFFFFu, mx[mt][0], o));
                mx[mt][1] = fmaxf(mx[mt][1], __shfl_xor_sync(0xFFFFFFFFu, mx[mt][1], o));
            }
        if (quad == 0) {
#pragma unroll
            for (int mt = 0; mt < 2; mt++) {
                pmax[warpN * 128 + warpM * 32 + mt * 16 + grp]     = mx[mt][0];
                pmax[warpN * 128 + warpM * 32 + mt * 16 + grp + 8] = mx[mt][1];
            }
        }
        __syncthreads();
        if (tid < 128) {
            float tm = fmaxf(fmaxf(pmax[tid], pmax[128 + tid]),
                             fmaxf(pmax[256 + tid], pmax[384 + tid]));
            const float om = run_m[tid];
            const float nm = fmaxf(om, tm);
            resc[tid]  = __expf(om - nm);
            run_m[tid] = nm;
        }
        __syncthreads();

        // ---- P = exp(S - m) (masked), row sums, store rounded P ----
        float sm[2][2] = {{0.f, 0.f}, {0.f, 0.f}};
#pragma unroll
        for (int mt = 0; mt < 2; mt++)
#pragma unroll
            for (int p = 0; p < 2; p++) {
                const int row = warpM * 32 + mt * 16 + grp + p * 8;
                const float nm = run_m[row];
#pragma unroll
                for (int nt = 0; nt < 4; nt++) {
                    const int n = warpN * 32 + nt * 8 + quad * 2;
                    const bool ok0 = !diag || n     <= row;
                    const bool ok1 = !diag || n + 1 <= row;
                    const float p0 = ok0 ? __expf(acc[mt][nt][p*2+0] - nm) : 0.f;
                    const float p1 = ok1 ? __expf(acc[mt][nt][p*2+1] - nm) : 0.f;
                    sm[mt][p] += p0 + p1;
                    *(float2*)&Ps[row * PS_LD + n] = make_float2(rndf(p0), rndf(p1));
                }
            }
#pragma unroll
        for (int o = 1; o <= 2; o <<= 1)
#pragma unroll
            for (int mt = 0; mt < 2; mt++) {
                sm[mt][0] += __shfl_xor_sync(0xFFFFFFFFu, sm[mt][0], o);
                sm[mt][1] += __shfl_xor_sync(0xFFFFFFFFu, sm[mt][1], o);
            }
        if (quad == 0) {
#pragma unroll
            for (int mt = 0; mt < 2; mt++) {
                psum[warpN * 128 + warpM * 32 + mt * 16 + grp]     = sm[mt][0];
                psum[warpN * 128 + warpM * 32 + mt * 16 + grp + 8] = sm[mt][1];
            }
        }

        // ---- rescale O by r ----
#pragma unroll
        for (int mt = 0; mt < 2; mt++) {
            const float r0 = resc[warpM * 32 + mt * 16 + grp];
            const float r1 = resc[warpM * 32 + mt * 16 + grp + 8];
#pragma unroll
            for (int nt = 0; nt < 2; nt++) {
                acc_o[mt][nt][0] *= r0; acc_o[mt][nt][1] *= r0;
                acc_o[mt][nt][2] *= r1; acc_o[mt][nt][3] *= r1;
            }
        }
        __syncthreads();
        if (tid < 128)
            run_s[tid] = run_s[tid] * resc[tid]
                       + psum[tid] + psum[128 + tid] + psum[256 + tid] + psum[384 + tid];

        // ---- PV: O += P @ V (K = 128), frag double-buffered ----
        {
            uint32_t pa[2][2][4];
            uint32_t pbb[2][2][2];
#pragma unroll
            for (int mt = 0; mt < 2; mt++)
                ldsm4(pa[0][mt][0], pa[0][mt][1], pa[0][mt][2], pa[0][mt][3],
                      sP0 + paRow + mt * TSP);
            ldsm4(pbb[0][0][0], pbb[0][0][1], pbb[0][1][0], pbb[0][1][1], sV0 + pbRow);
#pragma unroll
            for (int ks = 0; ks < 16; ks++) {
                const int cur = ks & 1, nxt = cur ^ 1;
                if (ks < 15) {
                    const uint32_t ko = (uint32_t)((ks + 1) * 32);
#pragma unroll
                    for (int mt = 0; mt < 2; mt++)
                        ldsm4(pa[nxt][mt][0], pa[nxt][mt][1], pa[nxt][mt][2], pa[nxt][mt][3],
                              sP0 + paRow + mt * TSP + ko);
                    ldsm4(pbb[nxt][0][0], pbb[nxt][0][1], pbb[nxt][1][0], pbb[nxt][1][1],
                          sV0 + pbRow + ko);
                }
#pragma unroll
                for (int mt = 0; mt < 2; mt++)
#pragma unroll
                    for (int nt = 0; nt < 2; nt++)
                        mma_tf32(acc_o[mt][nt], pa[cur][mt], pbb[cur][nt]);
            }
        }
        __syncthreads();    // protect Ps/Vs before next tj overwrites
    }

    // ---- final normalize + write concat layout ----
#pragma unroll
    for (int mt = 0; mt < 2; mt++) {
        const int lr0 = warpM * 32 + mt * 16 + grp;
        const float inv0 = 1.0f / run_s[lr0];
        const float inv1 = 1.0f / run_s[lr0 + 8];
        const int l0 = bm + lr0;
#pragma unroll
        for (int nt = 0; nt < 2; nt++) {
            const int d = warpN * 16 + nt * 8 + quad * 2;
            float* dst0 = g_outcat + ((size_t)l0 * 4 + bv) * DD + kv * DHH + d;
            float* dst1 = g_outcat + ((size_t)(l0 + 8) * 4 + bv) * DD + kv * DHH + d;
            dst0[0] = rndf(acc_o[mt][nt][0] * inv0); dst0[1] = rndf(acc_o[mt][nt][1] * inv0);
            dst1[0] = rndf(acc_o[mt][nt][2] * inv1); dst1[1] = rndf(acc_o[mt][nt][3] * inv1);
        }
    }
}

// ---------------------------------------------------------------------------
// Prep: single launch rounding x, Wi, Wo.
// ---------------------------------------------------------------------------
#define N4_X  (RR * DD / 4)
#define N4_WI (PD * DD / 4)
#define N4_WO (DD * DD / 4)
#define N4_ALL (N4_X + N4_WI + N4_WO)

__global__ void round_all(const float* __restrict__ x, const float* __restrict__ Wi,
                          const float* __restrict__ Wo)
{
    int i = blockIdx.x * blockDim.x + threadIdx.x;
    if (i >= N4_ALL) return;
    const float4* src; float4* dst; int j = i;
    if (j < N4_X)                 { src = (const float4*)x;  dst = (float4*)g_xr;  }
    else if ((j -= N4_X) < N4_WI) { src = (const float4*)Wi; dst = (float4*)g_wir; }
    else { j -= N4_WI;              src = (const float4*)Wo; dst = (float4*)g_wor; }
    float4 v = src[j];
    v.x = rndf(v.x); v.y = rndf(v.y); v.z = rndf(v.z); v.w = rndf(v.w);
    dst[j] = v;
}

// Merged w1 + w2 transpose (rounded): z<16 -> w1 [64x1024], z>=16 -> w2 [1024x1024]
__global__ void transpose_w12(const float* __restrict__ w1, const float* __restrict__ w2)
{
    __shared__ float t[32][33];
    const int z = blockIdx.z;
    const float* src; float* dst; int R, C;
    if (z < NHH) {
        if (blockIdx.y >= 2) return;                 // w1 has only 64 rows
        src = w1 + (size_t)z * DHH * LL;  dst = g_w1t + (size_t)z * LL * DHH;
        R = DHH; C = LL;
    } else {
        src = w2 + (size_t)(z - NHH) * LL * LL;  dst = g_w2t + (size_t)(z - NHH) * LL * LL;
        R = LL; C = LL;
    }
    const int c0 = blockIdx.x * 32, r0 = blockIdx.y * 32;
    const int tx = threadIdx.x, ty = threadIdx.y;
#pragma unroll
    for (int j = 0; j < 32; j += 8)
        t[ty + j][tx] = rndf(src[(size_t)(r0 + ty + j) * C + c0 + tx]);
    __syncthreads();
#pragma unroll
    for (int j = 0; j < 32; j += 8)
        dst[(size_t)(c0 + ty + j) * R + r0 + tx] = t[tx][ty + j];
}

// g_vt[bv][dcol][m] = proj[(m*4+bv)*PD + DD + dcol]  (already rounded)
__global__ void transpose_v()
{
    __shared__ float t[32][33];
    const int bv = blockIdx.z;
    const int c0 = blockIdx.x * 32, r0 = blockIdx.y * 32;
    const int tx = threadIdx.x, ty = threadIdx.y;
#pragma unroll
    for (int j = 0; j < 32; j += 8)
        t[ty + j][tx] = g_proj[((size_t)(r0 + ty + j) * 4 + bv) * PD + DD + c0 + tx];
    __syncthreads();
#pragma unroll
    for (int j = 0; j < 32; j += 8)
        g_vt[(size_t)bv * LL * LL + (size_t)(c0 + ty + j) * LL + r0 + tx] = t[tx][ty + j];
}

// ---------------------------------------------------------------------------
extern "C" void kernel_launch(void* const* d_in, const int* in_sizes, int n_in,
                              void* d_out, int out_size)
{
    (void)in_sizes; (void)n_in; (void)out_size;
    const float* x  = (const float*)d_in[0];
    // d_in[1] = attention_mask (exactly causal; implemented structurally)
    const float* Wi = (const float*)d_in[2];
    const float* bi = (const float*)d_in[3];
    const float* w1 = (const float*)d_in[4];
    const float* b1 = (const float*)d_in[5];
    const float* w2 = (const float*)d_in[6];
    const float* b2 = (const float*)d_in[7];
    const float* Wo = (const float*)d_in[8];
    const float* bo = (const float*)d_in[9];
    float* out = (float*)d_out;

    float *proj, *hid, *w1t, *w2t, *xr, *wir, *wor, *outcat;
    cudaGetSymbolAddress((void**)&proj,   g_proj);
    cudaGetSymbolAddress((void**)&hid,    g_hid);
    cudaGetSymbolAddress((void**)&w1t,    g_w1t);
    cudaGetSymbolAddress((void**)&w2t,    g_w2t);
    cudaGetSymbolAddress((void**)&xr,     g_xr);
    cudaGetSymbolAddress((void**)&wir,    g_wir);
    cudaGetSymbolAddress((void**)&wor,    g_wor);
    cudaGetSymbolAddress((void**)&outcat, g_outcat);

    cudaFuncSetAttribute(gemm_mma,   cudaFuncAttributeMaxDynamicSharedMemorySize, SMEM_BYTES);
    cudaFuncSetAttribute(attn_fused, cudaFuncAttributeMaxDynamicSharedMemorySize, ATTN_SMEM_BYTES);

    // 1: round x/Wi/Wo (pre-rounding keeps all mma mainloops cvt-free)
    round_all<<<(N4_ALL + 255) / 256, 256>>>(x, Wi, Wo);
    // 2: merged weight transposes to K-major (rounded)
    transpose_w12<<<dim3(32, 32, 2 * NHH), dim3(32, 8)>>>(w1, w2);
    // 3: K1 proj = x @ Wi^T + bi               (4096 x 2048 x 1024)
    gemm_mma<<<dim3(PD/128, RR/128), 256, SMEM_BYTES>>>(0, DD, 0, xr, wir, bi, proj);
    // 4: V^T per batch
    transpose_v<<<dim3(32, 32, BSZ), dim3(32, 8)>>>();
    // 5: K2 hid = rnd(relu(q @ w1 + b1))       (16 x [4096 x 1024 x 64])
    gemm_mma<<<dim3(LL/128, RR/128, NHH), 256, SMEM_BYTES>>>(1, DHH, 1, proj, w1t, b1, hid);
    // 6: fused logits + softmax + PV           (512 CTAs, 512 thr, LPT order)
    attn_fused<<<8 * NB, 512, ATTN_SMEM_BYTES>>>(b2);
    // 7: K6 y = outcat @ Wo^T + bo             (4096 x 1024 x 1024)
    gemm_mma<<<dim3(DD/128, RR/128), 256, SMEM_BYTES>>>(3, DD, 0, outcat, wor, bo, out);
}

// round 16
// speedup vs baseline: 1.0239x; 1.0239x over previous
#include <cuda_runtime.h>
#include <cstdint>
#include <math.h>

// Shapes (fixed by the problem)
#define LL   1024
#define BSZ  4
#define DD   1024
#define NHH  16
#define DHH  64
#define PD   2048          // 2*D
#define RR   4096          // L*BS
#define NB   64            // BS*NH batch count for attention

// Scratch (device globals: allocation-free kernel_launch)
__device__ float g_proj[(size_t)RR * PD];            // 32 MB (tf32-rounded)
__device__ float g_hid [(size_t)NHH * RR * LL];      // 268 MB (tf32-rounded)
__device__ float g_outcat[(size_t)RR * DD];          // 17 MB (tf32-rounded)
__device__ float g_w1t[(size_t)NHH * LL * DHH];      // 4 MB  (rounded)
__device__ float g_w2t[(size_t)NHH * LL * LL];       // 64 MB (rounded)
__device__ float g_xr [(size_t)RR * DD];             // 16 MB (x rounded)
__device__ float g_wir[(size_t)PD * DD];             // 8 MB  (Wi rounded)
__device__ float g_wor[(size_t)DD * DD];             // 4 MB  (Wo rounded)
__device__ float g_vt [(size_t)BSZ * LL * LL];       // 16 MB (V^T per batch, rounded)

// ---------------------------------------------------------------------------
__device__ __forceinline__ uint32_t f2tf32(float f) {
    uint32_t u;
    asm("cvt.rna.tf32.f32 %0, %1;" : "=r"(u) : "f"(f));
    return u;
}
__device__ __forceinline__ float rndf(float f) { return __uint_as_float(f2tf32(f)); }

__device__ __forceinline__ uint32_t smem_u32(const void* p) {
    uint32_t a;
    asm("{ .reg .u64 t; cvta.to.shared.u64 t, %1; cvt.u32.u64 %0, t; }" : "=r"(a) : "l"(p));
    return a;
}
__device__ __forceinline__ void cp_async16(uint32_t dst, const void* src) {
    asm volatile("cp.async.cg.shared.global [%0], [%1], 16;" :: "r"(dst), "l"(src));
}
__device__ __forceinline__ void cp_commit() {
    asm volatile("cp.async.commit_group;" ::: "memory");
}
__device__ __forceinline__ void cp_wait1() {
    asm volatile("cp.async.wait_group 1;" ::: "memory");
}
__device__ __forceinline__ void ldsm4(uint32_t& r0, uint32_t& r1, uint32_t& r2, uint32_t& r3,
                                      uint32_t addr) {
    asm volatile("ldmatrix.sync.aligned.m8n8.x4.shared.b16 {%0,%1,%2,%3}, [%4];"
                 : "=r"(r0), "=r"(r1), "=r"(r2), "=r"(r3) : "r"(addr));
}
__device__ __forceinline__ void mma_tf32(float c[4], const uint32_t a[4], const uint32_t b[2]) {
    asm volatile(
        "mma.sync.aligned.m16n8k8.row.col.f32.tf32.tf32.f32 "
        "{%0,%1,%2,%3}, {%4,%5,%6,%7}, {%8,%9}, {%0,%1,%2,%3};"
        : "+f"(c[0]), "+f"(c[1]), "+f"(c[2]), "+f"(c[3])
        : "r"(a[0]), "r"(a[1]), "r"(a[2]), "r"(a[3]), "r"(b[0]), "r"(b[1]));
}

#define PADK 36
#define TS   (16 * PADK * 4)                 // 16-row block stride (std smem)
#define PS_LD 132                            // padded row length for P/V tiles
#define TSP  (16 * PS_LD * 4)                // 16-row block stride (P/V smem)

// ---------------------------------------------------------------------------
// Generic 128x128-tile tf32 GEMM: C = act(A @ B^T + bias). Pre-rounded inputs.
// 3-stage cp.async, ldmatrix, frag double-buffer. 8 warps (4M x 2N).
// mode: 0=proj  1=hid(relu)  3=out
// ---------------------------------------------------------------------------
#define STAGE_F (128 * PADK)
#define SMEM_BYTES (2 * 3 * STAGE_F * 4)     // 110592

__global__ void __launch_bounds__(256, 2) gemm_mma(
    int mode, int K, int relu,
    const float* __restrict__ Ain, const float* __restrict__ Bin,
    const float* __restrict__ biasIn, float* __restrict__ Cout)
{
    const int bm = blockIdx.y * 128;
    const int bn = blockIdx.x * 128;

    const float* A; const float* B; const float* bias; float* C;
    size_t sA, sB, ldc;
    if (mode == 0) {            // proj = x @ Wi^T + bi
        A = Ain; sA = DD; B = Bin; sB = DD; bias = biasIn; C = Cout; ldc = PD;
    } else if (mode == 1) {     // hid[h] = relu(proj[:, h*64:] @ w1t[h]^T + b1[h])
        int h = blockIdx.z;
        A = Ain + h * DHH;                sA = PD;
        B = Bin + (size_t)h * LL * DHH;   sB = DHH;
        bias = biasIn + h * LL;
        C = Cout + (size_t)h * RR * LL;   ldc = LL;
    } else {                    // out = outcat @ Wo^T + bo
        A = Ain; sA = DD; B = Bin; sB = DD; bias = biasIn; C = Cout; ldc = DD;
    }

    extern __shared__ __align__(16) float smem[];
    float* As = smem;                    // [3][128][PADK]
    float* Bs = smem + 3 * STAGE_F;      // [3][128][PADK]

    const int tid   = threadIdx.x;
    const int wid   = tid >> 5, lane = tid & 31;
    const int warpM = wid & 3;
    const int warpN = wid >> 2;
    const int grp   = lane >> 2;
    const int quad  = lane & 3;

    const int T = K / 32;

    const uint32_t sA0 = smem_u32(As);
    const uint32_t sB0 = smem_u32(Bs);
    const uint32_t aRow = (uint32_t)(((warpM * 32 + (lane & 15)) * PADK + (lane >> 4) * 4) * 4);
    const uint32_t bRow = (uint32_t)(((warpN * 64 + ((lane >> 4) & 1) * 8 + (lane & 7)) * PADK
                                      + ((lane >> 3) & 1) * 4) * 4);

    auto issue = [&](int chunk, int buf) {
        const int k0 = chunk * 32;
        float* sa = As + buf * STAGE_F;
        float* sb = Bs + buf * STAGE_F;
#pragma unroll
        for (int j = 0; j < 4; j++) {
            const int idx = tid + j * 256;
            const int r = idx >> 3, c4 = (idx & 7) * 4;
            cp_async16(smem_u32(&sa[r * PADK + c4]),
                       &A[(size_t)(bm + r) * sA + k0 + c4]);
            cp_async16(smem_u32(&sb[r * PADK + c4]),
                       &B[(size_t)(bn + r) * sB + k0 + c4]);
        }
    };

    issue(0, 0); cp_commit();
    if (1 < T) issue(1, 1);
    cp_commit();

    float acc[2][8][4] = {};
    uint32_t af[2][2][4], bf[2][8][2];

#pragma unroll 1
    for (int t = 0; t < T; t++) {
        cp_wait1();
        __syncthreads();

        if (t + 2 < T) issue(t + 2, (t + 2) % 3);
        cp_commit();

        const uint32_t aSt = sA0 + (uint32_t)((t % 3) * STAGE_F * 4);
        const uint32_t bSt = sB0 + (uint32_t)((t % 3) * STAGE_F * 4);

#pragma unroll
        for (int mt = 0; mt < 2; mt++)
            ldsm4(af[0][mt][0], af[0][mt][1], af[0][mt][2], af[0][mt][3],
                  aSt + aRow + mt * TS);
#pragma unroll
        for (int p = 0; p < 4; p++)
            ldsm4(bf[0][2*p][0], bf[0][2*p][1], bf[0][2*p+1][0], bf[0][2*p+1][1],
                  bSt + bRow + p * TS);

#pragma unroll
        for (int ks = 0; ks < 4; ks++) {
            const int cur = ks & 1, nxt = cur ^ 1;
            if (ks < 3) {
                const uint32_t ko = (uint32_t)((ks + 1) * 32);
#pragma unroll
                for (int mt = 0; mt < 2; mt++)
                    ldsm4(af[nxt][mt][0], af[nxt][mt][1], af[nxt][mt][2], af[nxt][mt][3],
                          aSt + aRow + mt * TS + ko);
#pragma unroll
                for (int p = 0; p < 4; p++)
                    ldsm4(bf[nxt][2*p][0], bf[nxt][2*p][1], bf[nxt][2*p+1][0], bf[nxt][2*p+1][1],
                          bSt + bRow + p * TS + ko);
            }
#pragma unroll
            for (int mt = 0; mt < 2; mt++)
#pragma unroll
                for (int nt = 0; nt < 8; nt++)
                    mma_tf32(acc[mt][nt], af[cur][mt], bf[cur][nt]);
        }
    }

    const bool rnd_out = (mode < 2);
#pragma unroll
    for (int mt = 0; mt < 2; mt++) {
        const int m = bm + warpM * 32 + mt * 16 + grp;
#pragma unroll
        for (int nt = 0; nt < 8; nt++) {
            const int n = bn + warpN * 64 + nt * 8 + quad * 2;
            float b0 = bias[n], b1 = bias[n + 1];
            float2 v0 = make_float2(acc[mt][nt][0] + b0, acc[mt][nt][1] + b1);
            float2 v1 = make_float2(acc[mt][nt][2] + b0, acc[mt][nt][3] + b1);
            if (relu) {
                v0.x = fmaxf(v0.x, 0.f); v0.y = fmaxf(v0.y, 0.f);
                v1.x = fmaxf(v1.x, 0.f); v1.y = fmaxf(v1.y, 0.f);
            }
            if (rnd_out) {
                v0.x = rndf(v0.x); v0.y = rndf(v0.y);
                v1.x = rndf(v1.x); v1.y = rndf(v1.y);
            }
            *(float2*)&C[(size_t)m * ldc + n]       = v0;
            *(float2*)&C[(size_t)(m + 8) * ldc + n] = v1;
        }
    }
}

// ---------------------------------------------------------------------------
// Fused logits + online-softmax + PV, 512 threads (16 warps = full SM).
// S tile 128x128: warps 4M x 4N (32x32). O tile 128x64: warps 4M x 4N (32x16).
// (R10 exact form — the measured optimum of this session.)
// ---------------------------------------------------------------------------
#define ATTN_SMEM_BYTES ((2 * 3 * STAGE_F + 128 * PS_LD + 64 * PS_LD + 3 * 128 + 2 * 512) * 4)

__global__ void __launch_bounds__(512, 1) attn_fused(const float* __restrict__ b2)
{
    const int bx = blockIdx.x;
    const int ti = 7 - (bx >> 6);              // ti-major: heaviest wave first
    const int i  = bx & 63;
    const int kq = i >> 2, bq = i & 3;
    const int bv = i >> 4, kv = i & 15;
    const int bm = ti * 128;

    const float* Ahid = g_hid + (size_t)kq * RR * LL + bq * LL;    // stride 4*LL
    const float* Bw   = g_w2t + (size_t)kq * LL * LL;              // stride LL
    const float* bias = b2 + kq * LL;
    const float* Vt   = g_vt + (size_t)bv * LL * LL + (size_t)(kv * DHH) * LL;

    extern __shared__ __align__(16) float smem[];
    float* As    = smem;                       // [3][128][PADK]
    float* Bs    = As + 3 * STAGE_F;           // [3][128][PADK]
    float* Ps    = Bs + 3 * STAGE_F;           // [128][PS_LD]
    float* Vs    = Ps + 128 * PS_LD;           // [64][PS_LD]
    float* run_m = Vs + 64 * PS_LD;            // [128]
    float* run_s = run_m + 128;                // [128]
    float* resc  = run_s + 128;                // [128]
    float* pmax  = resc + 128;                 // [4][128]
    float* psum  = pmax + 512;                 // [4][128]

    const int tid   = threadIdx.x;
    const int wid   = tid >> 5, lane = tid & 31;
    const int warpM = wid & 3, warpN = wid >> 2;      // 4 x 4 warps
    const int grp   = lane >> 2, quad = lane & 3;

    if (tid < 128) { run_m[tid] = -1e30f; run_s[tid] = 0.f; }

    const uint32_t sA0 = smem_u32(As);
    const uint32_t sB0 = smem_u32(Bs);
    const uint32_t sP0 = smem_u32(Ps);
    const uint32_t sV0 = smem_u32(Vs);
    const uint32_t aRow = (uint32_t)(((warpM * 32 + (lane & 15)) * PADK + (lane >> 4) * 4) * 4);
    const uint32_t bRow = (uint32_t)(((warpN * 32 + ((lane >> 4) & 1) * 8 + (lane & 7)) * PADK
                                      + ((lane >> 3) & 1) * 4) * 4);
    const uint32_t paRow = (uint32_t)(((warpM * 32 + (lane & 15)) * PS_LD + (lane >> 4) * 4) * 4);
    const uint32_t pbRow = (uint32_t)(((warpN * 16 + ((lane >> 4) & 1) * 8 + (lane & 7)) * PS_LD
                                       + ((lane >> 3) & 1) * 4) * 4);

    float acc_o[2][2][4] = {};
    __syncthreads();

    for (int tj = 0; tj <= ti; tj++) {
        const int bn = tj * 128;

        // V tile: 64 rows x 128 cols = 2048 float4 (4 per thread).
#pragma unroll
        for (int j = 0; j < 4; j++) {
            const int idx = tid + j * 512;
            const int d = idx >> 5, c4 = (idx & 31) * 4;
            cp_async16(smem_u32(&Vs[d * PS_LD + c4]), &Vt[(size_t)d * LL + bn + c4]);
        }
        cp_commit();

        auto issueS = [&](int chunk, int buf) {
            const int k0 = chunk * 32;
            float* sa = As + buf * STAGE_F;
            float* sb = Bs + buf * STAGE_F;
#pragma unroll
            for (int j = 0; j < 2; j++) {
                const int idx = tid + j * 512;
                const int r = idx >> 3, c4 = (idx & 7) * 4;
                cp_async16(smem_u32(&sa[r * PADK + c4]),
                           &Ahid[(size_t)(bm + r) * (4 * LL) + k0 + c4]);
                cp_async16(smem_u32(&sb[r * PADK + c4]),
                           &Bw[(size_t)(bn + r) * LL + k0 + c4]);
            }
        };
        issueS(0, 0); cp_commit();
        issueS(1, 1); cp_commit();

        float acc[2][4][4] = {};
        {
            uint32_t af[2][2][4], bf[2][4][2];
#pragma unroll 1
            for (int t = 0; t < 32; t++) {
                cp_wait1();
                __syncthreads();
                if (t + 2 < 32) issueS(t + 2, (t + 2) % 3);
                cp_commit();

                const uint32_t aSt = sA0 + (uint32_t)((t % 3) * STAGE_F * 4);
                const uint32_t bSt = sB0 + (uint32_t)((t % 3) * STAGE_F * 4);

#pragma unroll
                for (int mt = 0; mt < 2; mt++)
                    ldsm4(af[0][mt][0], af[0][mt][1], af[0][mt][2], af[0][mt][3],
                          aSt + aRow + mt * TS);
#pragma unroll
                for (int p = 0; p < 2; p++)
                    ldsm4(bf[0][2*p][0], bf[0][2*p][1], bf[0][2*p+1][0], bf[0][2*p+1][1],
                          bSt + bRow + p * TS);

#pragma unroll
                for (int ks = 0; ks < 4; ks++) {
                    const int cur = ks & 1, nxt = cur ^ 1;
                    if (ks < 3) {
                        const uint32_t ko = (uint32_t)((ks + 1) * 32);
#pragma unroll
                        for (int mt = 0; mt < 2; mt++)
                            ldsm4(af[nxt][mt][0], af[nxt][mt][1], af[nxt][mt][2], af[nxt][mt][3],
                                  aSt + aRow + mt * TS + ko);
#pragma unroll
                        for (int p = 0; p < 2; p++)
                            ldsm4(bf[nxt][2*p][0], bf[nxt][2*p][1],
                                  bf[nxt][2*p+1][0], bf[nxt][2*p+1][1],
                                  bSt + bRow + p * TS + ko);
                    }
#pragma unroll
                    for (int mt = 0; mt < 2; mt++)
#pragma unroll
                        for (int nt = 0; nt < 4; nt++)
                            mma_tf32(acc[mt][nt], af[cur][mt], bf[cur][nt]);
                }
            }
        }

        // ---- bias + online-softmax stats ----
        const bool diag = (tj == ti);
#pragma unroll
        for (int nt = 0; nt < 4; nt++) {
            const int n = bn + warpN * 32 + nt * 8 + quad * 2;
            const float bb0 = bias[n], bb1 = bias[n + 1];
            acc[0][nt][0] += bb0; acc[0][nt][1] += bb1;
            acc[0][nt][2] += bb0; acc[0][nt][3] += bb1;
            acc[1][nt][0] += bb0; acc[1][nt][1] += bb1;
            acc[1][nt][2] += bb0; acc[1][nt][3] += bb1;
        }

        float mx[2][2];
#pragma unroll
        for (int mt = 0; mt < 2; mt++)
#pragma unroll
            for (int p = 0; p < 2; p++) {
                const int row = warpM * 32 + mt * 16 + grp + p * 8;
                float m = -1e30f;
#pragma unroll
                for (int nt = 0; nt < 4; nt++) {
                    const int n = warpN * 32 + nt * 8 + quad * 2;
                    if (!diag || n     <= row) m = fmaxf(m, acc[mt][nt][p * 2 + 0]);
                    if (!diag || n + 1 <= row) m = fmaxf(m, acc[mt][nt][p * 2 + 1]);
                }
                mx[mt][p] = m;
            }
#pragma unroll
        for (int o = 1; o <= 2; o <<= 1)
#pragma unroll
            for (int mt = 0; mt < 2; mt++) {
                mx[mt][0] = fmaxf(mx[mt][0], __shfl_xor_sync(0xFFFFFFFFu, mx[mt][0], o));
                mx[mt][1] = fmaxf(mx[mt][1], __shfl_xor_sync(0xFFFFFFFFu, mx[mt][1], o));
            }
        if (quad == 0) {
#pragma unroll
            for (int mt = 0; mt < 2; mt++) {
                pmax[warpN * 128 + warpM * 32 + mt * 16 + grp]     = mx[mt][0];
                pmax[warpN * 128 + warpM * 32 + mt * 16 + grp + 8] = mx[mt][1];
            }
        }
        __syncthreads();
        if (tid < 128) {
            float tm = fmaxf(fmaxf(pmax[tid], pmax[128 + tid]),
                             fmaxf(pmax[256 + tid], pmax[384 + tid]));
            const float om = run_m[tid];
            const float nm = fmaxf(om, tm);
            resc[tid]  = __expf(om - nm);
            run_m[tid] = nm;
        }
        __syncthreads();

        // ---- P = exp(S - m) (masked), row sums, store rounded P ----
        float sm[2][2] = {{0.f, 0.f}, {0.f, 0.f}};
#pragma unroll
        for (int mt = 0; mt < 2; mt++)
#pragma unroll
            for (int p = 0; p < 2; p++) {
                const int row = warpM * 32 + mt * 16 + grp + p * 8;
                const float nm = run_m[row];
#pragma unroll
                for (int nt = 0; nt < 4; nt++) {
                    const int n = warpN * 32 + nt * 8 + quad * 2;
                    const bool ok0 = !diag || n     <= row;
                    const bool ok1 = !diag || n + 1 <= row;
                    const float p0 = ok0 ? __expf(acc[mt][nt][p*2+0] - nm) : 0.f;
                    const float p1 = ok1 ? __expf(acc[mt][nt][p*2+1] - nm) : 0.f;
                    sm[mt][p] += p0 + p1;
                    *(float2*)&Ps[row * PS_LD + n] = make_float2(rndf(p0), rndf(p1));
                }
            }
#pragma unroll
        for (int o = 1; o <= 2; o <<= 1)
#pragma unroll
            for (int mt = 0; mt < 2; mt++) {
                sm[mt][0] += __shfl_xor_sync(0xFFFFFFFFu, sm[mt][0], o);
                sm[mt][1] += __shfl_xor_sync(0xFFFFFFFFu, sm[mt][1], o);
            }
        if (quad == 0) {
#pragma unroll
            for (int mt = 0; mt < 2; mt++) {
                psum[warpN * 128 + warpM * 32 + mt * 16 + grp]     = sm[mt][0];
                psum[warpN * 128 + warpM * 32 + mt * 16 + grp + 8] = sm[mt][1];
            }
        }

        // ---- rescale O by r ----
#pragma unroll
        for (int mt = 0; mt < 2; mt++) {
            const float r0 = resc[warpM * 32 + mt * 16 + grp];
            const float r1 = resc[warpM * 32 + mt * 16 + grp + 8];
#pragma unroll
            for (int nt = 0; nt < 2; nt++) {
                acc_o[mt][nt][0] *= r0; acc_o[mt][nt][1] *= r0;
                acc_o[mt][nt][2] *= r1; acc_o[mt][nt][3] *= r1;
            }
        }
        __syncthreads();
        if (tid < 128)
            run_s[tid] = run_s[tid] * resc[tid]
                       + psum[tid] + psum[128 + tid] + psum[256 + tid] + psum[384 + tid];

        // ---- PV: O += P @ V (K = 128), frag double-buffered ----
        {
            uint32_t pa[2][2][4];
            uint32_t pbb[2][2][2];
#pragma unroll
            for (int mt = 0; mt < 2; mt++)
                ldsm4(pa[0][mt][0], pa[0][mt][1], pa[0][mt][2], pa[0][mt][3],
                      sP0 + paRow + mt * TSP);
            ldsm4(pbb[0][0][0], pbb[0][0][1], pbb[0][1][0], pbb[0][1][1], sV0 + pbRow);
#pragma unroll
            for (int ks = 0; ks < 16; ks++) {
                const int cur = ks & 1, nxt = cur ^ 1;
                if (ks < 15) {
                    const uint32_t ko = (uint32_t)((ks + 1) * 32);
#pragma unroll
                    for (int mt = 0; mt < 2; mt++)
                        ldsm4(pa[nxt][mt][0], pa[nxt][mt][1], pa[nxt][mt][2], pa[nxt][mt][3],
                              sP0 + paRow + mt * TSP + ko);
                    ldsm4(pbb[nxt][0][0], pbb[nxt][0][1], pbb[nxt][1][0], pbb[nxt][1][1],
                          sV0 + pbRow + ko);
                }
#pragma unroll
                for (int mt = 0; mt < 2; mt++)
#pragma unroll
                    for (int nt = 0; nt < 2; nt++)
                        mma_tf32(acc_o[mt][nt], pa[cur][mt], pbb[cur][nt]);
            }
        }
        __syncthreads();    // protect Ps/Vs before next tj overwrites
    }

    // ---- final normalize + write concat layout ----
#pragma unroll
    for (int mt = 0; mt < 2; mt++) {
        const int lr0 = warpM * 32 + mt * 16 + grp;
        const float inv0 = 1.0f / run_s[lr0];
        const float inv1 = 1.0f / run_s[lr0 + 8];
        const int l0 = bm + lr0;
#pragma unroll
        for (int nt = 0; nt < 2; nt++) {
            const int d = warpN * 16 + nt * 8 + quad * 2;
            float* dst0 = g_outcat + ((size_t)l0 * 4 + bv) * DD + kv * DHH + d;
            float* dst1 = g_outcat + ((size_t)(l0 + 8) * 4 + bv) * DD + kv * DHH + d;
            dst0[0] = rndf(acc_o[mt][nt][0] * inv0); dst0[1] = rndf(acc_o[mt][nt][1] * inv0);
            dst1[0] = rndf(acc_o[mt][nt][2] * inv1); dst1[1] = rndf(acc_o[mt][nt][3] * inv1);
        }
    }
}

// ---------------------------------------------------------------------------
// Prep: single launch rounding x, Wi, Wo.
// ---------------------------------------------------------------------------
#define N4_X  (RR * DD / 4)
#define N4_WI (PD * DD / 4)
#define N4_WO (DD * DD / 4)
#define N4_ALL (N4_X + N4_WI + N4_WO)

__global__ void round_all(const float* __restrict__ x, const float* __restrict__ Wi,
                          const float* __restrict__ Wo)
{
    int i = blockIdx.x * blockDim.x + threadIdx.x;
    if (i >= N4_ALL) return;
    const float4* src; float4* dst; int j = i;
    if (j < N4_X)                 { src = (const float4*)x;  dst = (float4*)g_xr;  }
    else if ((j -= N4_X) < N4_WI) { src = (const float4*)Wi; dst = (float4*)g_wir; }
    else { j -= N4_WI;              src = (const float4*)Wo; dst = (float4*)g_wor; }
    float4 v = src[j];
    v.x = rndf(v.x); v.y = rndf(v.y); v.z = rndf(v.z); v.w = rndf(v.w);
    dst[j] = v;
}

__global__ void transpose_rk(const float* __restrict__ src, float* __restrict__ dst,
                             int R, int C)
{
    __shared__ float t[32][33];
    const size_t zo = (size_t)blockIdx.z * R * C;
    const int c0 = blockIdx.x * 32, r0 = blockIdx.y * 32;
    const int tx = threadIdx.x, ty = threadIdx.y;
#pragma unroll
    for (int j = 0; j < 32; j += 8)
        t[ty + j][tx] = rndf(src[zo + (size_t)(r0 + ty + j) * C + c0 + tx]);
    __syncthreads();
#pragma unroll
    for (int j = 0; j < 32; j += 8)
        dst[zo + (size_t)(c0 + ty + j) * R + r0 + tx] = t[tx][ty + j];
}

// g_vt[bv][dcol][m] = proj[(m*4+bv)*PD + DD + dcol]  (already rounded)
__global__ void transpose_v()
{
    __shared__ float t[32][33];
    const int bv = blockIdx.z;
    const int c0 = blockIdx.x * 32, r0 = blockIdx.y * 32;
    const int tx = threadIdx.x, ty = threadIdx.y;
#pragma unroll
    for (int j = 0; j < 32; j += 8)
        t[ty + j][tx] = g_proj[((size_t)(r0 + ty + j) * 4 + bv) * PD + DD + c0 + tx];
    __syncthreads();
#pragma unroll
    for (int j = 0; j < 32; j += 8)
        g_vt[(size_t)bv * LL * LL + (size_t)(c0 + ty + j) * LL + r0 + tx] = t[tx][ty + j];
}

// ---------------------------------------------------------------------------
extern "C" void kernel_launch(void* const* d_in, const int* in_sizes, int n_in,
                              void* d_out, int out_size)
{
    (void)in_sizes; (void)n_in; (void)out_size;
    const float* x  = (const float*)d_in[0];
    // d_in[1] = attention_mask (exactly causal; implemented structurally)
    const float* Wi = (const float*)d_in[2];
    const float* bi = (const float*)d_in[3];
    const float* w1 = (const float*)d_in[4];
    const float* b1 = (const float*)d_in[5];
    const float* w2 = (const float*)d_in[6];
    const float* b2 = (const float*)d_in[7];
    const float* Wo = (const float*)d_in[8];
    const float* bo = (const float*)d_in[9];
    float* out = (float*)d_out;

    float *proj, *hid, *w1t, *w2t, *xr, *wir, *wor, *outcat;
    cudaGetSymbolAddress((void**)&proj,   g_proj);
    cudaGetSymbolAddress((void**)&hid,    g_hid);
    cudaGetSymbolAddress((void**)&w1t,    g_w1t);
    cudaGetSymbolAddress((void**)&w2t,    g_w2t);
    cudaGetSymbolAddress((void**)&xr,     g_xr);
    cudaGetSymbolAddress((void**)&wir,    g_wir);
    cudaGetSymbolAddress((void**)&wor,    g_wor);
    cudaGetSymbolAddress((void**)&outcat, g_outcat);

    cudaFuncSetAttribute(gemm_mma,   cudaFuncAttributeMaxDynamicSharedMemorySize, SMEM_BYTES);
    cudaFuncSetAttribute(attn_fused, cudaFuncAttributeMaxDynamicSharedMemorySize, ATTN_SMEM_BYTES);

    // 1: round x/Wi/Wo (pre-rounding keeps all mma mainloops cvt-free)
    round_all<<<(N4_ALL + 255) / 256, 256>>>(x, Wi, Wo);
    // 2,3: weight transposes to K-major (rounded)
    transpose_rk<<<dim3(32, 2, NHH),  dim3(32, 8)>>>(w1, w1t, DHH, LL);
    transpose_rk<<<dim3(32, 32, NHH), dim3(32, 8)>>>(w2, w2t, LL, LL);
    // 4: K1 proj = x @ Wi^T + bi               (4096 x 2048 x 1024)
    gemm_mma<<<dim3(PD/128, RR/128), 256, SMEM_BYTES>>>(0, DD, 0, xr, wir, bi, proj);
    // 5: V^T per batch
    transpose_v<<<dim3(32, 32, BSZ), dim3(32, 8)>>>();
    // 6: K2 hid = rnd(relu(q @ w1 + b1))       (16 x [4096 x 1024 x 64])
    gemm_mma<<<dim3(LL/128, RR/128, NHH), 256, SMEM_BYTES>>>(1, DHH, 1, proj, w1t, b1, hid);
    // 7: fused logits + softmax + PV           (512 CTAs, 512 thr, LPT order)
    attn_fused<<<8 * NB, 512, ATTN_SMEM_BYTES>>>(b2);
    // 8: K6 y = outcat @ Wo^T + bo             (4096 x 1024 x 1024)
    gemm_mma<<<dim3(DD/128, RR/128), 256, SMEM_BYTES>>>(3, DD, 0, outcat, wor, bo, out);
}